// round 15
// baseline (speedup 1.0000x reference)
#include <cuda_runtime.h>
#include <cuda_fp16.h>
#include <cstdint>

using u32 = unsigned int;

// Problem constants: B=16, C=64, H=W=64
static constexpr int B_  = 16;
static constexpr int HW_ = 4096;   // 64*64
static constexpr int SP_ = 1024;   // pooled spatial (32*32)

// ---------------- scratch (__device__ globals; no allocation) ----------------
__device__ __align__(16) __half d_theta[B_ * HW_ * 8];   // [b][p][8]
__device__ __align__(16) __half d_phi_t[B_ * SP_ * 8];   // [b][s][8]
__device__ __align__(16) __half d_g_t  [B_ * 32 * SP_];  // [b][v][s]

// ---------------- small helpers ----------------
__device__ __forceinline__ u32 packh(float lo, float hi) {
    __half2 v = __floats2half2_rn(lo, hi);
    return *reinterpret_cast<u32*>(&v);
}
__device__ __forceinline__ u32 hadd2u(u32 a, u32 b) {
    __half2 r = __hadd2(*reinterpret_cast<__half2*>(&a),
                        *reinterpret_cast<__half2*>(&b));
    return *reinterpret_cast<u32*>(&r);
}
__device__ __forceinline__ u32 hmax2u(u32 a, u32 b) {
    __half2 r = __hmax2(*reinterpret_cast<__half2*>(&a),
                        *reinterpret_cast<__half2*>(&b));
    return *reinterpret_cast<u32*>(&r);
}
__device__ __forceinline__ uint4 max4u(uint4 a, uint4 b, uint4 c, uint4 d) {
    uint4 r;
    r.x = hmax2u(hmax2u(a.x, b.x), hmax2u(c.x, d.x));
    r.y = hmax2u(hmax2u(a.y, b.y), hmax2u(c.y, d.y));
    r.z = hmax2u(hmax2u(a.z, b.z), hmax2u(c.z, d.z));
    r.w = hmax2u(hmax2u(a.w, b.w), hmax2u(c.w, d.w));
    return r;
}
// fp16-space Schraudolph exp, two at once: low 16 bits of f are fp16 bits of exp(x).
__device__ __forceinline__ u32 fexp2pack(float x0, float x1) {
    float f0 = fmaf(x0, 1477.3197f, 12598228.0f);
    float f1 = fmaf(x1, 1477.3197f, 12598228.0f);
    return __byte_perm(__float_as_uint(f0), __float_as_uint(f1), 0x5410);
}
// mma.m16n8k8 f16 inputs, f32 accum
__device__ __forceinline__ void mma_k8h(float* d, u32 a0, u32 a1, u32 b0) {
    asm volatile(
        "mma.sync.aligned.m16n8k8.row.col.f32.f16.f16.f32 "
        "{%0,%1,%2,%3}, {%4,%5}, {%6}, {%7,%8,%9,%10};\n"
        : "=f"(d[0]), "=f"(d[1]), "=f"(d[2]), "=f"(d[3])
        : "r"(a0), "r"(a1), "r"(b0),
          "f"(0.f), "f"(0.f), "f"(0.f), "f"(0.f));
}
// mma.m16n8k16 f16 inputs, f32 accum
__device__ __forceinline__ void mma_k16h(float* d, u32 a0, u32 a1, u32 a2, u32 a3,
                                         u32 b0, u32 b1) {
    asm volatile(
        "mma.sync.aligned.m16n8k16.row.col.f32.f16.f16.f32 "
        "{%0,%1,%2,%3}, {%4,%5,%6,%7}, {%8,%9}, {%0,%1,%2,%3};\n"
        : "+f"(d[0]), "+f"(d[1]), "+f"(d[2]), "+f"(d[3])
        : "r"(a0), "r"(a1), "r"(a2), "r"(a3), "r"(b0), "r"(b1));
}
// mma.m16n8k16 f16 inputs, f16 accum
__device__ __forceinline__ void mma_k16hh(u32& d0, u32& d1, u32 a0, u32 a1, u32 a2, u32 a3,
                                          u32 b0, u32 b1) {
    asm volatile(
        "mma.sync.aligned.m16n8k16.row.col.f16.f16.f16.f16 "
        "{%0,%1}, {%2,%3,%4,%5}, {%6,%7}, {%0,%1};\n"
        : "+r"(d0), "+r"(d1)
        : "r"(a0), "r"(a1), "r"(a2), "r"(a3), "r"(b0), "r"(b1));
}
__device__ __forceinline__ void ldsm_x4(u32& r0, u32& r1, u32& r2, u32& r3, u32 a) {
    asm volatile("ldmatrix.sync.aligned.m8n8.x4.shared.b16 {%0,%1,%2,%3}, [%4];"
                 : "=r"(r0), "=r"(r1), "=r"(r2), "=r"(r3) : "r"(a));
}
__device__ __forceinline__ void ldsm_x2(u32& r0, u32& r1, u32 a) {
    asm volatile("ldmatrix.sync.aligned.m8n8.x2.shared.b16 {%0,%1}, [%2];"
                 : "=r"(r0), "=r"(r1) : "r"(a));
}
__device__ __forceinline__ void ldsm_x4_t(u32& r0, u32& r1, u32& r2, u32& r3, u32 a) {
    asm volatile("ldmatrix.sync.aligned.m8n8.x4.trans.shared.b16 {%0,%1,%2,%3}, [%4];"
                 : "=r"(r0), "=r"(r1), "=r"(r2), "=r"(r3) : "r"(a));
}

// ---------------- kernel 1: projections (tensor cores) + fused 2x2 pool ----------------
static constexpr int XS_S = 136;
static constexpr int WS_S = 72;
static constexpr int DS_S = 56;

__global__ void __launch_bounds__(256) proj_kernel(
    const float* __restrict__ x,
    const float* __restrict__ Wt, const float* __restrict__ Wp,
    const float* __restrict__ Wg)
{
    __shared__ __align__(16) __half xs [64 * XS_S];
    __shared__ __align__(16) __half Ws [48 * WS_S];
    __shared__ __align__(16) __half dsm[128 * DS_S];

    int tid = threadIdx.x;
    int b   = blockIdx.y;
    int r   = blockIdx.x;          // pooled row
    int p0  = r * 128;

    for (int i = tid; i < 1536; i += 256) {
        int j = i >> 5, cp = i & 31;
        const float* Wsrc = (j < 8) ? &Wt[j * 64]
                          : (j < 16) ? &Wp[(j - 8) * 64]
                                     : &Wg[(j - 16) * 64];
        float2 v = *reinterpret_cast<const float2*>(&Wsrc[2 * cp]);
        *reinterpret_cast<u32*>(&Ws[j * WS_S + 2 * cp]) = packh(v.x, v.y);
    }
    const float* xb = x + (size_t)b * 64 * HW_ + p0;
#pragma unroll
    for (int it = 0; it < 16; it++) {
        int flat = it * 256 + tid;
        int c = flat >> 6, pp = flat & 63;
        float2 v = *reinterpret_cast<const float2*>(&xb[(size_t)c * HW_ + 2 * pp]);
        *reinterpret_cast<u32*>(&xs[c * XS_S + 2 * pp]) = packh(v.x, v.y);
    }
    __syncthreads();

    int w = tid >> 5, lane = tid & 31;
    int g4 = lane >> 2, tg = lane & 3;
    int pw = w * 16;

    int mi = lane >> 3, rr = lane & 7;
    int half8 = (mi & 1) * 8;
    int oth8  = (mi >> 1) * 8;
    u32 xs_a = (u32)__cvta_generic_to_shared(xs);
    u32 ws_a = (u32)__cvta_generic_to_shared(Ws);
    u32 b_base = xs_a + ((half8 + rr) * XS_S + pw + oth8) * 2;

    float acc[3][2][4];
#pragma unroll
    for (int m = 0; m < 3; m++)
#pragma unroll
        for (int n = 0; n < 2; n++)
#pragma unroll
            for (int e = 0; e < 4; e++) acc[m][n][e] = 0.f;

#pragma unroll
    for (int ks = 0; ks < 4; ks++) {
        int k0 = ks * 16;
        u32 b0n0, b1n0, b0n1, b1n1;
        ldsm_x4_t(b0n0, b1n0, b0n1, b1n1, b_base + k0 * XS_S * 2);
#pragma unroll
        for (int m = 0; m < 3; m++) {
            u32 A0, A1, A2, A3;
            ldsm_x4(A0, A1, A2, A3,
                    ws_a + ((m * 16 + half8 + rr) * WS_S + k0 + oth8) * 2);
            mma_k16h(acc[m][0], A0, A1, A2, A3, b0n0, b1n0);
            mma_k16h(acc[m][1], A0, A1, A2, A3, b0n1, b1n1);
        }
    }

#pragma unroll
    for (int m = 0; m < 3; m++)
#pragma unroll
        for (int nt = 0; nt < 2; nt++) {
            int j = m * 16 + g4;
            int p = pw + nt * 8 + 2 * tg;
            dsm[p * DS_S + j]           = __float2half(acc[m][nt][0]);
            dsm[(p + 1) * DS_S + j]     = __float2half(acc[m][nt][1]);
            dsm[p * DS_S + j + 8]       = __float2half(acc[m][nt][2]);
            dsm[(p + 1) * DS_S + j + 8] = __float2half(acc[m][nt][3]);
        }
    __syncthreads();

    if (tid < 128) {
        reinterpret_cast<uint4*>(d_theta)[(size_t)b * HW_ + p0 + tid] =
            *reinterpret_cast<const uint4*>(&dsm[tid * DS_S]);
        if (tid >= 96) {
            int j2 = tid - 96;
            int pA = 2 * j2, pC = 64 + 2 * j2;
            uint4 m = max4u(*reinterpret_cast<const uint4*>(&dsm[pA * DS_S + 8]),
                            *reinterpret_cast<const uint4*>(&dsm[(pA + 1) * DS_S + 8]),
                            *reinterpret_cast<const uint4*>(&dsm[pC * DS_S + 8]),
                            *reinterpret_cast<const uint4*>(&dsm[(pC + 1) * DS_S + 8]));
            reinterpret_cast<uint4*>(d_phi_t)[(size_t)b * SP_ + r * 32 + j2] = m;
        }
    } else {
        int i  = tid - 128;
        int j2 = i & 31, vq = i >> 5;
        int pA = 2 * j2, pC = 64 + 2 * j2;
        int off = 16 + 8 * vq;
        uint4 m = max4u(*reinterpret_cast<const uint4*>(&dsm[pA * DS_S + off]),
                        *reinterpret_cast<const uint4*>(&dsm[(pA + 1) * DS_S + off]),
                        *reinterpret_cast<const uint4*>(&dsm[pC * DS_S + off]),
                        *reinterpret_cast<const uint4*>(&dsm[(pC + 1) * DS_S + off]));
        int s = r * 32 + j2;
        __half* gt = d_g_t + ((size_t)b * 32 << 10) + s;
        const __half2* h = reinterpret_cast<const __half2*>(&m);
#pragma unroll
        for (int e = 0; e < 4; e++) {
            int v = vq * 8 + 2 * e;
            gt[(size_t)v << 10]       = __low2half(h[e]);
            gt[(size_t)(v + 1) << 10] = __high2half(h[e]);
        }
    }
}

// ---------------- kernel 2: fused attention + output projection + residual ----------------
// 256 queries/CTA, 2 q-tiles/warp. Keys in 2 chunks of 512. ldmatrix mainloop.
// Row sums via HADD2 on the FMA pipe (replaces 2 HMMA/iter -> -17% tensor work).
static constexpr int KC       = 512;
static constexpr int G_STRIDE = 520;
static constexpr int ATTN_SMEM = KC * 8 * 2 + 32 * G_STRIDE * 2;  // 41472
static constexpr int OSM_S = 40;
static constexpr int WO_S  = 34;

__global__ void __launch_bounds__(256, 3) attn_out_kernel(
    const float* __restrict__ x, const float* __restrict__ Wo,
    const float* __restrict__ gamma_p, float* __restrict__ out)
{
    extern __shared__ __align__(16) char smem[];
    __half* phi_s = reinterpret_cast<__half*>(smem);               // [key][8]
    __half* g_s   = reinterpret_cast<__half*>(smem + KC * 8 * 2);  // [v][520]
    // epilogue overlays:
    __half* osm = reinterpret_cast<__half*>(smem);                 // 256*40*2 = 20480 B
    __half* wsm = reinterpret_cast<__half*>(smem + 20480);         // 64*34*2  =  4352 B

    int b   = blockIdx.y;
    int tid = threadIdx.x;

    int w    = tid >> 5;
    int lane = tid & 31;
    int g4   = lane >> 2;
    int tg   = lane & 3;
    int qb   = blockIdx.x * 256 + w * 32;   // 2 q-tiles per warp
    int q0   = qb + g4;
    int q1   = qb + 16 + g4;

    const __half* th = d_theta + (size_t)(b * HW_) * 8;
    u32 a0 = *reinterpret_cast<const u32*>(th + (size_t)q0 * 8 + 2 * tg);
    u32 a1 = *reinterpret_cast<const u32*>(th + (size_t)(q0 + 8) * 8 + 2 * tg);
    u32 a2 = *reinterpret_cast<const u32*>(th + (size_t)q1 * 8 + 2 * tg);
    u32 a3 = *reinterpret_cast<const u32*>(th + (size_t)(q1 + 8) * 8 + 2 * tg);

    u32 o0[8], o1[8];
#pragma unroll
    for (int i = 0; i < 8; i++) { o0[i] = 0u; o1[i] = 0u; }
    // f16x2 per-thread row-sum accumulators (quad-reduced at the end)
    u32 sA0 = 0u, sA1 = 0u, sB0 = 0u, sB1 = 0u;

    // ldmatrix lane addresses
    u32 phi_a0 = (u32)__cvta_generic_to_shared(phi_s) + (lane & 15) * 16;
    int mrow = lane >> 3, rrow = lane & 7;
    int v0   = (mrow >> 1) * 8 + rrow;
    int cofs = (mrow & 1) * 8;
    u32 g_a0 = (u32)__cvta_generic_to_shared(g_s) + (v0 * G_STRIDE + cofs) * 2;
    u32 g_a1 = g_a0 + 16 * G_STRIDE * 2;

#pragma unroll 1
    for (int chunk = 0; chunk < 2; chunk++) {
        if (chunk) __syncthreads();
        {
            const uint4* src = reinterpret_cast<const uint4*>(d_phi_t)
                               + (size_t)b * SP_ + chunk * KC;
            uint4* dst = reinterpret_cast<uint4*>(phi_s);
#pragma unroll
            for (int it = 0; it < 2; it++) dst[it * 256 + tid] = src[it * 256 + tid];
        }
        {
            const uint4* src = reinterpret_cast<const uint4*>(d_g_t)
                               + (size_t)b * 32 * 128 + chunk * 64;
            uint4* dst = reinterpret_cast<uint4*>(g_s);
#pragma unroll
            for (int it = 0; it < 8; it++) {
                int i = it * 256 + tid;
                int v = i >> 6, col = i & 63;
                dst[v * 65 + col] = src[v * 128 + col];
            }
        }
        __syncthreads();

#pragma unroll 2
        for (int kb = 0; kb < KC; kb += 16) {
            u32 pb0, pb1;
            ldsm_x2(pb0, pb1, phi_a0 + kb * 16);

            float s0[4], s1v[4], s2[4], s3[4];
            mma_k8h(s0,  a0, a1, pb0);
            mma_k8h(s1v, a0, a1, pb1);
            mma_k8h(s2,  a2, a3, pb0);
            mma_k8h(s3,  a2, a3, pb1);

            u32 pa0 = fexp2pack(s0[0],  s0[1]);
            u32 pa1 = fexp2pack(s0[2],  s0[3]);
            u32 pa2 = fexp2pack(s1v[0], s1v[1]);
            u32 pa3 = fexp2pack(s1v[2], s1v[3]);
            u32 qa0 = fexp2pack(s2[0],  s2[1]);
            u32 qa1 = fexp2pack(s2[2],  s2[3]);
            u32 qa2 = fexp2pack(s3[0],  s3[1]);
            u32 qa3 = fexp2pack(s3[2],  s3[3]);

            // row sums on FMA pipe: pa0/pa2 are this thread's P-fragment of row q0,
            // pa1/pa3 of row q0+8 (likewise qa for tile 1)
            sA0 = hadd2u(sA0, hadd2u(pa0, pa2));
            sA1 = hadd2u(sA1, hadd2u(pa1, pa3));
            sB0 = hadd2u(sB0, hadd2u(qa0, qa2));
            sB1 = hadd2u(sB1, hadd2u(qa1, qa3));

            u32 gA0, gA1, gA2, gA3, gB0, gB1, gB2, gB3;
            ldsm_x4(gA0, gA1, gA2, gA3, g_a0 + kb * 2);
            ldsm_x4(gB0, gB1, gB2, gB3, g_a1 + kb * 2);

            mma_k16hh(o0[0], o0[1], pa0, pa1, pa2, pa3, gA0, gA1);
            mma_k16hh(o0[2], o0[3], pa0, pa1, pa2, pa3, gA2, gA3);
            mma_k16hh(o0[4], o0[5], pa0, pa1, pa2, pa3, gB0, gB1);
            mma_k16hh(o0[6], o0[7], pa0, pa1, pa2, pa3, gB2, gB3);
            mma_k16hh(o1[0], o1[1], qa0, qa1, qa2, qa3, gA0, gA1);
            mma_k16hh(o1[2], o1[3], qa0, qa1, qa2, qa3, gA2, gA3);
            mma_k16hh(o1[4], o1[5], qa0, qa1, qa2, qa3, gB0, gB1);
            mma_k16hh(o1[6], o1[7], qa0, qa1, qa2, qa3, gB2, gB3);
        }
    }

    // quad-reduce row sums (tg lanes hold disjoint keys), then fold f16x2 halves
    sA0 = hadd2u(sA0, __shfl_xor_sync(0xffffffffu, sA0, 1));
    sA0 = hadd2u(sA0, __shfl_xor_sync(0xffffffffu, sA0, 2));
    sA1 = hadd2u(sA1, __shfl_xor_sync(0xffffffffu, sA1, 1));
    sA1 = hadd2u(sA1, __shfl_xor_sync(0xffffffffu, sA1, 2));
    sB0 = hadd2u(sB0, __shfl_xor_sync(0xffffffffu, sB0, 1));
    sB0 = hadd2u(sB0, __shfl_xor_sync(0xffffffffu, sB0, 2));
    sB1 = hadd2u(sB1, __shfl_xor_sync(0xffffffffu, sB1, 1));
    sB1 = hadd2u(sB1, __shfl_xor_sync(0xffffffffu, sB1, 2));

    float gm = *gamma_p;
    __half2 h;
    h = *reinterpret_cast<__half2*>(&sA0);
    float iA0 = __fdividef(gm, __low2float(h) + __high2float(h));
    h = *reinterpret_cast<__half2*>(&sA1);
    float iA1 = __fdividef(gm, __low2float(h) + __high2float(h));
    h = *reinterpret_cast<__half2*>(&sB0);
    float iB0 = __fdividef(gm, __low2float(h) + __high2float(h));
    h = *reinterpret_cast<__half2*>(&sB1);
    float iB1 = __fdividef(gm, __low2float(h) + __high2float(h));

    // ---- stage normalized, gamma-folded o into smem (overlay) ----
    __syncthreads();
    {
        int ql0 = w * 32 + g4;
        int ql1 = w * 32 + 16 + g4;
#pragma unroll
        for (int j = 0; j < 4; j++) {
            int v = 8 * j + 2 * tg;
            float2 f;
            f = __half22float2(*reinterpret_cast<__half2*>(&o0[2 * j]));
            *reinterpret_cast<u32*>(&osm[ql0 * OSM_S + v]) = packh(f.x * iA0, f.y * iA0);
            f = __half22float2(*reinterpret_cast<__half2*>(&o0[2 * j + 1]));
            *reinterpret_cast<u32*>(&osm[(ql0 + 8) * OSM_S + v]) = packh(f.x * iA1, f.y * iA1);
            f = __half22float2(*reinterpret_cast<__half2*>(&o1[2 * j]));
            *reinterpret_cast<u32*>(&osm[ql1 * OSM_S + v]) = packh(f.x * iB0, f.y * iB0);
            f = __half22float2(*reinterpret_cast<__half2*>(&o1[2 * j + 1]));
            *reinterpret_cast<u32*>(&osm[(ql1 + 8) * OSM_S + v]) = packh(f.x * iB1, f.y * iB1);
        }
    }
    for (int i = tid; i < 64 * 32; i += 256) {
        int c = i >> 5, v = i & 31;
        wsm[c * WO_S + v] = __float2half(Wo[c * 32 + v]);
    }
    __syncthreads();

    // ---- epilogue: out[c][p] = Wo @ o^T + x (register-light, per-m tiles) ----
    int p0 = blockIdx.x * 256;
    const float* xb = x + (size_t)b * 64 * HW_;
    float* outb     = out + (size_t)b * 64 * HW_;

#pragma unroll 1
    for (int hh = 0; hh < 2; hh++) {
        int ph = w * 32 + hh * 16;

        u32 Bf[2][2][2];
#pragma unroll
        for (int nt = 0; nt < 2; nt++) {
            int qr = (ph + nt * 8 + g4) * OSM_S;
#pragma unroll
            for (int ks = 0; ks < 2; ks++) {
                Bf[nt][ks][0] = *reinterpret_cast<const u32*>(&osm[qr + ks * 16 + 2 * tg]);
                Bf[nt][ks][1] = *reinterpret_cast<const u32*>(&osm[qr + ks * 16 + 8 + 2 * tg]);
            }
        }

#pragma unroll
        for (int m = 0; m < 4; m++) {
            float acc[2][4];
#pragma unroll
            for (int n = 0; n < 2; n++)
#pragma unroll
                for (int e = 0; e < 4; e++) acc[n][e] = 0.f;

#pragma unroll
            for (int ks = 0; ks < 2; ks++) {
                int r0 = (m * 16 + g4) * WO_S + ks * 16 + 2 * tg;
                int r1 = (m * 16 + g4 + 8) * WO_S + ks * 16 + 2 * tg;
                u32 A0 = *reinterpret_cast<const u32*>(&wsm[r0]);
                u32 A1 = *reinterpret_cast<const u32*>(&wsm[r1]);
                u32 A2 = *reinterpret_cast<const u32*>(&wsm[r0 + 8]);
                u32 A3 = *reinterpret_cast<const u32*>(&wsm[r1 + 8]);
                mma_k16h(acc[0], A0, A1, A2, A3, Bf[0][ks][0], Bf[0][ks][1]);
                mma_k16h(acc[1], A0, A1, A2, A3, Bf[1][ks][0], Bf[1][ks][1]);
            }

#pragma unroll
            for (int nt = 0; nt < 2; nt++) {
                int c = m * 16 + g4;
                int p = p0 + ph + nt * 8 + 2 * tg;
                size_t i1 = (size_t)c * HW_ + p;
                size_t i2 = (size_t)(c + 8) * HW_ + p;
                float2 xv1 = *reinterpret_cast<const float2*>(&xb[i1]);
                float2 xv2 = *reinterpret_cast<const float2*>(&xb[i2]);
                float2 r1 = make_float2(acc[nt][0] + xv1.x, acc[nt][1] + xv1.y);
                float2 r2 = make_float2(acc[nt][2] + xv2.x, acc[nt][3] + xv2.y);
                *reinterpret_cast<float2*>(&outb[i1]) = r1;
                *reinterpret_cast<float2*>(&outb[i2]) = r2;
            }
        }
    }
}

// ---------------- launch ----------------
extern "C" void kernel_launch(void* const* d_in, const int* in_sizes, int n_in,
                              void* d_out, int out_size)
{
    const float* x     = (const float*)d_in[0];
    const float* Wt    = (const float*)d_in[1];
    const float* Wp    = (const float*)d_in[2];
    const float* Wg    = (const float*)d_in[3];
    const float* Wo    = (const float*)d_in[4];
    const float* gamma = (const float*)d_in[5];
    float* out = (float*)d_out;

    proj_kernel<<<dim3(32, 16), 256>>>(x, Wt, Wp, Wg);

    cudaFuncSetAttribute(attn_out_kernel, cudaFuncAttributeMaxDynamicSharedMemorySize, ATTN_SMEM);
    attn_out_kernel<<<dim3(16, 16), 256, ATTN_SMEM>>>(x, Wo, gamma, out);
}

// round 16
// speedup vs baseline: 1.3474x; 1.3474x over previous
#include <cuda_runtime.h>
#include <cuda_fp16.h>
#include <cstdint>

using u32 = unsigned int;

// Problem constants: B=16, C=64, H=W=64
static constexpr int B_  = 16;
static constexpr int HW_ = 4096;   // 64*64
static constexpr int SP_ = 1024;   // pooled spatial (32*32)

// ---------------- scratch (__device__ globals; no allocation) ----------------
__device__ __align__(16) __half d_theta[B_ * HW_ * 8];   // [b][p][8]
__device__ __align__(16) __half d_phi_t[B_ * SP_ * 8];   // [b][s][8]
__device__ __align__(16) __half d_g_t  [B_ * 32 * SP_];  // [b][v][s]

// ---------------- small helpers ----------------
__device__ __forceinline__ u32 packh(float lo, float hi) {
    __half2 v = __floats2half2_rn(lo, hi);
    return *reinterpret_cast<u32*>(&v);
}
__device__ __forceinline__ u32 hmax2u(u32 a, u32 b) {
    __half2 r = __hmax2(*reinterpret_cast<__half2*>(&a),
                        *reinterpret_cast<__half2*>(&b));
    return *reinterpret_cast<u32*>(&r);
}
__device__ __forceinline__ uint4 max4u(uint4 a, uint4 b, uint4 c, uint4 d) {
    uint4 r;
    r.x = hmax2u(hmax2u(a.x, b.x), hmax2u(c.x, d.x));
    r.y = hmax2u(hmax2u(a.y, b.y), hmax2u(c.y, d.y));
    r.z = hmax2u(hmax2u(a.z, b.z), hmax2u(c.z, d.z));
    r.w = hmax2u(hmax2u(a.w, b.w), hmax2u(c.w, d.w));
    return r;
}
// fp16-space Schraudolph exp, two at once: low 16 bits of f are fp16 bits of exp(x).
__device__ __forceinline__ u32 fexp2pack(float x0, float x1) {
    float f0 = fmaf(x0, 1477.3197f, 12598228.0f);
    float f1 = fmaf(x1, 1477.3197f, 12598228.0f);
    return __byte_perm(__float_as_uint(f0), __float_as_uint(f1), 0x5410);
}
// mma.m16n8k8 f16 inputs, f32 accum
__device__ __forceinline__ void mma_k8h(float* d, u32 a0, u32 a1, u32 b0) {
    asm volatile(
        "mma.sync.aligned.m16n8k8.row.col.f32.f16.f16.f32 "
        "{%0,%1,%2,%3}, {%4,%5}, {%6}, {%7,%8,%9,%10};\n"
        : "=f"(d[0]), "=f"(d[1]), "=f"(d[2]), "=f"(d[3])
        : "r"(a0), "r"(a1), "r"(b0),
          "f"(0.f), "f"(0.f), "f"(0.f), "f"(0.f));
}
// mma.m16n8k16 f16 inputs, f32 accum
__device__ __forceinline__ void mma_k16h(float* d, u32 a0, u32 a1, u32 a2, u32 a3,
                                         u32 b0, u32 b1) {
    asm volatile(
        "mma.sync.aligned.m16n8k16.row.col.f32.f16.f16.f32 "
        "{%0,%1,%2,%3}, {%4,%5,%6,%7}, {%8,%9}, {%0,%1,%2,%3};\n"
        : "+f"(d[0]), "+f"(d[1]), "+f"(d[2]), "+f"(d[3])
        : "r"(a0), "r"(a1), "r"(a2), "r"(a3), "r"(b0), "r"(b1));
}
// mma.m16n8k16 f16 inputs, f16 accum
__device__ __forceinline__ void mma_k16hh(u32& d0, u32& d1, u32 a0, u32 a1, u32 a2, u32 a3,
                                          u32 b0, u32 b1) {
    asm volatile(
        "mma.sync.aligned.m16n8k16.row.col.f16.f16.f16.f16 "
        "{%0,%1}, {%2,%3,%4,%5}, {%6,%7}, {%0,%1};\n"
        : "+r"(d0), "+r"(d1)
        : "r"(a0), "r"(a1), "r"(a2), "r"(a3), "r"(b0), "r"(b1));
}
__device__ __forceinline__ void ldsm_x4(u32& r0, u32& r1, u32& r2, u32& r3, u32 a) {
    asm volatile("ldmatrix.sync.aligned.m8n8.x4.shared.b16 {%0,%1,%2,%3}, [%4];"
                 : "=r"(r0), "=r"(r1), "=r"(r2), "=r"(r3) : "r"(a));
}
__device__ __forceinline__ void ldsm_x2(u32& r0, u32& r1, u32 a) {
    asm volatile("ldmatrix.sync.aligned.m8n8.x2.shared.b16 {%0,%1}, [%2];"
                 : "=r"(r0), "=r"(r1) : "r"(a));
}
__device__ __forceinline__ void ldsm_x4_t(u32& r0, u32& r1, u32& r2, u32& r3, u32 a) {
    asm volatile("ldmatrix.sync.aligned.m8n8.x4.trans.shared.b16 {%0,%1,%2,%3}, [%4];"
                 : "=r"(r0), "=r"(r1), "=r"(r2), "=r"(r3) : "r"(a));
}

// ---------------- kernel 1: projections (tensor cores) + fused 2x2 pool ----------------
static constexpr int XS_S = 136;
static constexpr int WS_S = 72;
static constexpr int DS_S = 56;

__global__ void __launch_bounds__(256) proj_kernel(
    const float* __restrict__ x,
    const float* __restrict__ Wt, const float* __restrict__ Wp,
    const float* __restrict__ Wg)
{
    __shared__ __align__(16) __half xs [64 * XS_S];
    __shared__ __align__(16) __half Ws [48 * WS_S];
    __shared__ __align__(16) __half dsm[128 * DS_S];

    int tid = threadIdx.x;
    int b   = blockIdx.y;
    int r   = blockIdx.x;          // pooled row
    int p0  = r * 128;

    for (int i = tid; i < 1536; i += 256) {
        int j = i >> 5, cp = i & 31;
        const float* Wsrc = (j < 8) ? &Wt[j * 64]
                          : (j < 16) ? &Wp[(j - 8) * 64]
                                     : &Wg[(j - 16) * 64];
        float2 v = *reinterpret_cast<const float2*>(&Wsrc[2 * cp]);
        *reinterpret_cast<u32*>(&Ws[j * WS_S + 2 * cp]) = packh(v.x, v.y);
    }
    const float* xb = x + (size_t)b * 64 * HW_ + p0;
#pragma unroll
    for (int it = 0; it < 16; it++) {
        int flat = it * 256 + tid;
        int c = flat >> 6, pp = flat & 63;
        float2 v = *reinterpret_cast<const float2*>(&xb[(size_t)c * HW_ + 2 * pp]);
        *reinterpret_cast<u32*>(&xs[c * XS_S + 2 * pp]) = packh(v.x, v.y);
    }
    __syncthreads();

    int w = tid >> 5, lane = tid & 31;
    int g4 = lane >> 2, tg = lane & 3;
    int pw = w * 16;

    int mi = lane >> 3, rr = lane & 7;
    int half8 = (mi & 1) * 8;
    int oth8  = (mi >> 1) * 8;
    u32 xs_a = (u32)__cvta_generic_to_shared(xs);
    u32 ws_a = (u32)__cvta_generic_to_shared(Ws);
    u32 b_base = xs_a + ((half8 + rr) * XS_S + pw + oth8) * 2;

    float acc[3][2][4];
#pragma unroll
    for (int m = 0; m < 3; m++)
#pragma unroll
        for (int n = 0; n < 2; n++)
#pragma unroll
            for (int e = 0; e < 4; e++) acc[m][n][e] = 0.f;

#pragma unroll
    for (int ks = 0; ks < 4; ks++) {
        int k0 = ks * 16;
        u32 b0n0, b1n0, b0n1, b1n1;
        ldsm_x4_t(b0n0, b1n0, b0n1, b1n1, b_base + k0 * XS_S * 2);
#pragma unroll
        for (int m = 0; m < 3; m++) {
            u32 A0, A1, A2, A3;
            ldsm_x4(A0, A1, A2, A3,
                    ws_a + ((m * 16 + half8 + rr) * WS_S + k0 + oth8) * 2);
            mma_k16h(acc[m][0], A0, A1, A2, A3, b0n0, b1n0);
            mma_k16h(acc[m][1], A0, A1, A2, A3, b0n1, b1n1);
        }
    }

#pragma unroll
    for (int m = 0; m < 3; m++)
#pragma unroll
        for (int nt = 0; nt < 2; nt++) {
            int j = m * 16 + g4;
            int p = pw + nt * 8 + 2 * tg;
            dsm[p * DS_S + j]           = __float2half(acc[m][nt][0]);
            dsm[(p + 1) * DS_S + j]     = __float2half(acc[m][nt][1]);
            dsm[p * DS_S + j + 8]       = __float2half(acc[m][nt][2]);
            dsm[(p + 1) * DS_S + j + 8] = __float2half(acc[m][nt][3]);
        }
    __syncthreads();

    if (tid < 128) {
        reinterpret_cast<uint4*>(d_theta)[(size_t)b * HW_ + p0 + tid] =
            *reinterpret_cast<const uint4*>(&dsm[tid * DS_S]);
        if (tid >= 96) {
            int j2 = tid - 96;
            int pA = 2 * j2, pC = 64 + 2 * j2;
            uint4 m = max4u(*reinterpret_cast<const uint4*>(&dsm[pA * DS_S + 8]),
                            *reinterpret_cast<const uint4*>(&dsm[(pA + 1) * DS_S + 8]),
                            *reinterpret_cast<const uint4*>(&dsm[pC * DS_S + 8]),
                            *reinterpret_cast<const uint4*>(&dsm[(pC + 1) * DS_S + 8]));
            reinterpret_cast<uint4*>(d_phi_t)[(size_t)b * SP_ + r * 32 + j2] = m;
        }
    } else {
        int i  = tid - 128;
        int j2 = i & 31, vq = i >> 5;
        int pA = 2 * j2, pC = 64 + 2 * j2;
        int off = 16 + 8 * vq;
        uint4 m = max4u(*reinterpret_cast<const uint4*>(&dsm[pA * DS_S + off]),
                        *reinterpret_cast<const uint4*>(&dsm[(pA + 1) * DS_S + off]),
                        *reinterpret_cast<const uint4*>(&dsm[pC * DS_S + off]),
                        *reinterpret_cast<const uint4*>(&dsm[(pC + 1) * DS_S + off]));
        int s = r * 32 + j2;
        __half* gt = d_g_t + ((size_t)b * 32 << 10) + s;
        const __half2* h = reinterpret_cast<const __half2*>(&m);
#pragma unroll
        for (int e = 0; e < 4; e++) {
            int v = vq * 8 + 2 * e;
            gt[(size_t)v << 10]       = __low2half(h[e]);
            gt[(size_t)(v + 1) << 10] = __high2half(h[e]);
        }
    }
}

// ---------------- kernel 2: fused attention + output projection + residual ----------------
// R14 mainloop (ldmatrix + ONES-mma sums) with 128-thread CTAs: 128 q/CTA, 32 q/warp
// unchanged, grid 512 CTAs -> 5 CTAs/SM by smem (207 KB), 20 warps/SM (occ +45%).
static constexpr int KC       = 512;
static constexpr int G_STRIDE = 520;
static constexpr int ATTN_SMEM = KC * 8 * 2 + 32 * G_STRIDE * 2;  // 41472
static constexpr int OSM_S = 40;
static constexpr int WO_S  = 34;

__global__ void __launch_bounds__(128, 5) attn_out_kernel(
    const float* __restrict__ x, const float* __restrict__ Wo,
    const float* __restrict__ gamma_p, float* __restrict__ out)
{
    extern __shared__ __align__(16) char smem[];
    __half* phi_s = reinterpret_cast<__half*>(smem);               // [key][8]
    __half* g_s   = reinterpret_cast<__half*>(smem + KC * 8 * 2);  // [v][520]
    // epilogue overlays:
    __half* osm = reinterpret_cast<__half*>(smem);                 // 128*40*2 = 10240 B
    __half* wsm = reinterpret_cast<__half*>(smem + 10240);         // 64*34*2  =  4352 B

    int b   = blockIdx.y;
    int tid = threadIdx.x;

    int w    = tid >> 5;        // 0..3
    int lane = tid & 31;
    int g4   = lane >> 2;
    int tg   = lane & 3;
    int qb   = blockIdx.x * 128 + w * 32;   // 2 q-tiles per warp
    int q0   = qb + g4;
    int q1   = qb + 16 + g4;

    const __half* th = d_theta + (size_t)(b * HW_) * 8;
    u32 a0 = *reinterpret_cast<const u32*>(th + (size_t)q0 * 8 + 2 * tg);
    u32 a1 = *reinterpret_cast<const u32*>(th + (size_t)(q0 + 8) * 8 + 2 * tg);
    u32 a2 = *reinterpret_cast<const u32*>(th + (size_t)q1 * 8 + 2 * tg);
    u32 a3 = *reinterpret_cast<const u32*>(th + (size_t)(q1 + 8) * 8 + 2 * tg);

    const u32 ONES = 0x3C003C00u;  // f16x2 {1,1}

    u32 o0[8], o1[8];
#pragma unroll
    for (int i = 0; i < 8; i++) { o0[i] = 0u; o1[i] = 0u; }
    u32 sm0[2] = {0u, 0u}, sm1[2] = {0u, 0u};

    // ldmatrix lane addresses
    u32 phi_a0 = (u32)__cvta_generic_to_shared(phi_s) + (lane & 15) * 16;
    int mrow = lane >> 3, rrow = lane & 7;
    int v0   = (mrow >> 1) * 8 + rrow;
    int cofs = (mrow & 1) * 8;
    u32 g_a0 = (u32)__cvta_generic_to_shared(g_s) + (v0 * G_STRIDE + cofs) * 2;
    u32 g_a1 = g_a0 + 16 * G_STRIDE * 2;

#pragma unroll 1
    for (int chunk = 0; chunk < 2; chunk++) {
        if (chunk) __syncthreads();   // prior chunk fully consumed before overwrite
        // load phi chunk: 512 uint4
        {
            const uint4* src = reinterpret_cast<const uint4*>(d_phi_t)
                               + (size_t)b * SP_ + chunk * KC;
            uint4* dst = reinterpret_cast<uint4*>(phi_s);
#pragma unroll
            for (int it = 0; it < 4; it++) dst[it * 128 + tid] = src[it * 128 + tid];
        }
        // load g chunk: 32 rows x 64 uint4 -> padded rows of 65 uint4
        {
            const uint4* src = reinterpret_cast<const uint4*>(d_g_t)
                               + (size_t)b * 32 * 128 + chunk * 64;
            uint4* dst = reinterpret_cast<uint4*>(g_s);
#pragma unroll
            for (int it = 0; it < 16; it++) {
                int i = it * 128 + tid;
                int v = i >> 6, col = i & 63;
                dst[v * 65 + col] = src[v * 128 + col];
            }
        }
        __syncthreads();

#pragma unroll 2
        for (int kb = 0; kb < KC; kb += 16) {
            u32 pb0, pb1;
            ldsm_x2(pb0, pb1, phi_a0 + kb * 16);

            float s0[4], s1v[4], s2[4], s3[4];
            mma_k8h(s0,  a0, a1, pb0);
            mma_k8h(s1v, a0, a1, pb1);
            mma_k8h(s2,  a2, a3, pb0);
            mma_k8h(s3,  a2, a3, pb1);

            u32 pa0 = fexp2pack(s0[0],  s0[1]);
            u32 pa1 = fexp2pack(s0[2],  s0[3]);
            u32 pa2 = fexp2pack(s1v[0], s1v[1]);
            u32 pa3 = fexp2pack(s1v[2], s1v[3]);
            u32 qa0 = fexp2pack(s2[0],  s2[1]);
            u32 qa1 = fexp2pack(s2[2],  s2[3]);
            u32 qa2 = fexp2pack(s3[0],  s3[1]);
            u32 qa3 = fexp2pack(s3[2],  s3[3]);

            mma_k16hh(sm0[0], sm0[1], pa0, pa1, pa2, pa3, ONES, ONES);
            mma_k16hh(sm1[0], sm1[1], qa0, qa1, qa2, qa3, ONES, ONES);

            u32 gA0, gA1, gA2, gA3, gB0, gB1, gB2, gB3;
            ldsm_x4(gA0, gA1, gA2, gA3, g_a0 + kb * 2);
            ldsm_x4(gB0, gB1, gB2, gB3, g_a1 + kb * 2);

            mma_k16hh(o0[0], o0[1], pa0, pa1, pa2, pa3, gA0, gA1);
            mma_k16hh(o0[2], o0[3], pa0, pa1, pa2, pa3, gA2, gA3);
            mma_k16hh(o0[4], o0[5], pa0, pa1, pa2, pa3, gB0, gB1);
            mma_k16hh(o0[6], o0[7], pa0, pa1, pa2, pa3, gB2, gB3);
            mma_k16hh(o1[0], o1[1], qa0, qa1, qa2, qa3, gA0, gA1);
            mma_k16hh(o1[2], o1[3], qa0, qa1, qa2, qa3, gA2, gA3);
            mma_k16hh(o1[4], o1[5], qa0, qa1, qa2, qa3, gB0, gB1);
            mma_k16hh(o1[6], o1[7], qa0, qa1, qa2, qa3, gB2, gB3);
        }
    }

    float gm = *gamma_p;
    float iA0 = __fdividef(gm, __low2float(*reinterpret_cast<__half2*>(&sm0[0])));
    float iA1 = __fdividef(gm, __low2float(*reinterpret_cast<__half2*>(&sm0[1])));
    float iB0 = __fdividef(gm, __low2float(*reinterpret_cast<__half2*>(&sm1[0])));
    float iB1 = __fdividef(gm, __low2float(*reinterpret_cast<__half2*>(&sm1[1])));

    // ---- stage normalized, gamma-folded o into smem (overlay) ----
    __syncthreads();
    {
        int ql0 = w * 32 + g4;
        int ql1 = w * 32 + 16 + g4;
#pragma unroll
        for (int j = 0; j < 4; j++) {
            int v = 8 * j + 2 * tg;
            float2 f;
            f = __half22float2(*reinterpret_cast<__half2*>(&o0[2 * j]));
            *reinterpret_cast<u32*>(&osm[ql0 * OSM_S + v]) = packh(f.x * iA0, f.y * iA0);
            f = __half22float2(*reinterpret_cast<__half2*>(&o0[2 * j + 1]));
            *reinterpret_cast<u32*>(&osm[(ql0 + 8) * OSM_S + v]) = packh(f.x * iA1, f.y * iA1);
            f = __half22float2(*reinterpret_cast<__half2*>(&o1[2 * j]));
            *reinterpret_cast<u32*>(&osm[ql1 * OSM_S + v]) = packh(f.x * iB0, f.y * iB0);
            f = __half22float2(*reinterpret_cast<__half2*>(&o1[2 * j + 1]));
            *reinterpret_cast<u32*>(&osm[(ql1 + 8) * OSM_S + v]) = packh(f.x * iB1, f.y * iB1);
        }
    }
    for (int i = tid; i < 64 * 32; i += 128) {
        int c = i >> 5, v = i & 31;
        wsm[c * WO_S + v] = __float2half(Wo[c * 32 + v]);
    }
    __syncthreads();

    // ---- epilogue: out[c][p] = Wo @ o^T + x (register-light, per-m tiles) ----
    int p0 = blockIdx.x * 128;
    const float* xb = x + (size_t)b * 64 * HW_;
    float* outb     = out + (size_t)b * 64 * HW_;

#pragma unroll 1
    for (int hh = 0; hh < 2; hh++) {
        int ph = w * 32 + hh * 16;

        u32 Bf[2][2][2];
#pragma unroll
        for (int nt = 0; nt < 2; nt++) {
            int qr = (ph + nt * 8 + g4) * OSM_S;
#pragma unroll
            for (int ks = 0; ks < 2; ks++) {
                Bf[nt][ks][0] = *reinterpret_cast<const u32*>(&osm[qr + ks * 16 + 2 * tg]);
                Bf[nt][ks][1] = *reinterpret_cast<const u32*>(&osm[qr + ks * 16 + 8 + 2 * tg]);
            }
        }

#pragma unroll
        for (int m = 0; m < 4; m++) {
            float acc[2][4];
#pragma unroll
            for (int n = 0; n < 2; n++)
#pragma unroll
                for (int e = 0; e < 4; e++) acc[n][e] = 0.f;

#pragma unroll
            for (int ks = 0; ks < 2; ks++) {
                int r0 = (m * 16 + g4) * WO_S + ks * 16 + 2 * tg;
                int r1 = (m * 16 + g4 + 8) * WO_S + ks * 16 + 2 * tg;
                u32 A0 = *reinterpret_cast<const u32*>(&wsm[r0]);
                u32 A1 = *reinterpret_cast<const u32*>(&wsm[r1]);
                u32 A2 = *reinterpret_cast<const u32*>(&wsm[r0 + 8]);
                u32 A3 = *reinterpret_cast<const u32*>(&wsm[r1 + 8]);
                mma_k16h(acc[0], A0, A1, A2, A3, Bf[0][ks][0], Bf[0][ks][1]);
                mma_k16h(acc[1], A0, A1, A2, A3, Bf[1][ks][0], Bf[1][ks][1]);
            }

#pragma unroll
            for (int nt = 0; nt < 2; nt++) {
                int c = m * 16 + g4;
                int p = p0 + ph + nt * 8 + 2 * tg;
                size_t i1 = (size_t)c * HW_ + p;
                size_t i2 = (size_t)(c + 8) * HW_ + p;
                float2 xv1 = *reinterpret_cast<const float2*>(&xb[i1]);
                float2 xv2 = *reinterpret_cast<const float2*>(&xb[i2]);
                float2 r1 = make_float2(acc[nt][0] + xv1.x, acc[nt][1] + xv1.y);
                float2 r2 = make_float2(acc[nt][2] + xv2.x, acc[nt][3] + xv2.y);
                *reinterpret_cast<float2*>(&outb[i1]) = r1;
                *reinterpret_cast<float2*>(&outb[i2]) = r2;
            }
        }
    }
}

// ---------------- launch ----------------
extern "C" void kernel_launch(void* const* d_in, const int* in_sizes, int n_in,
                              void* d_out, int out_size)
{
    const float* x     = (const float*)d_in[0];
    const float* Wt    = (const float*)d_in[1];
    const float* Wp    = (const float*)d_in[2];
    const float* Wg    = (const float*)d_in[3];
    const float* Wo    = (const float*)d_in[4];
    const float* gamma = (const float*)d_in[5];
    float* out = (float*)d_out;

    proj_kernel<<<dim3(32, 16), 256>>>(x, Wt, Wp, Wg);

    cudaFuncSetAttribute(attn_out_kernel, cudaFuncAttributeMaxDynamicSharedMemorySize, ATTN_SMEM);
    attn_out_kernel<<<dim3(32, 16), 128, ATTN_SMEM>>>(x, Wo, gamma, out);
}

// round 17
// speedup vs baseline: 1.4657x; 1.0878x over previous
#include <cuda_runtime.h>
#include <cuda_fp16.h>
#include <cstdint>

using u32 = unsigned int;

// Problem constants: B=16, C=64, H=W=64
static constexpr int B_  = 16;
static constexpr int HW_ = 4096;   // 64*64
static constexpr int SP_ = 1024;   // pooled spatial (32*32)

// ---------------- scratch (__device__ globals; no allocation) ----------------
__device__ __align__(16) __half d_theta[B_ * HW_ * 8];   // [b][p][8]
__device__ __align__(16) __half d_phi_t[B_ * SP_ * 8];   // [b][s][8]
__device__ __align__(16) __half d_g_t  [B_ * 32 * SP_];  // [b][v][s]

// ---------------- small helpers ----------------
__device__ __forceinline__ u32 packh(float lo, float hi) {
    __half2 v = __floats2half2_rn(lo, hi);
    return *reinterpret_cast<u32*>(&v);
}
__device__ __forceinline__ u32 hmax2u(u32 a, u32 b) {
    __half2 r = __hmax2(*reinterpret_cast<__half2*>(&a),
                        *reinterpret_cast<__half2*>(&b));
    return *reinterpret_cast<u32*>(&r);
}
__device__ __forceinline__ uint4 max4u(uint4 a, uint4 b, uint4 c, uint4 d) {
    uint4 r;
    r.x = hmax2u(hmax2u(a.x, b.x), hmax2u(c.x, d.x));
    r.y = hmax2u(hmax2u(a.y, b.y), hmax2u(c.y, d.y));
    r.z = hmax2u(hmax2u(a.z, b.z), hmax2u(c.z, d.z));
    r.w = hmax2u(hmax2u(a.w, b.w), hmax2u(c.w, d.w));
    return r;
}
// fp16-space Schraudolph exp, two at once: low 16 bits of f are fp16 bits of exp(x).
__device__ __forceinline__ u32 fexp2pack(float x0, float x1) {
    float f0 = fmaf(x0, 1477.3197f, 12598228.0f);
    float f1 = fmaf(x1, 1477.3197f, 12598228.0f);
    return __byte_perm(__float_as_uint(f0), __float_as_uint(f1), 0x5410);
}
// mma.m16n8k8 f16 inputs, f32 accum
__device__ __forceinline__ void mma_k8h(float* d, u32 a0, u32 a1, u32 b0) {
    asm volatile(
        "mma.sync.aligned.m16n8k8.row.col.f32.f16.f16.f32 "
        "{%0,%1,%2,%3}, {%4,%5}, {%6}, {%7,%8,%9,%10};\n"
        : "=f"(d[0]), "=f"(d[1]), "=f"(d[2]), "=f"(d[3])
        : "r"(a0), "r"(a1), "r"(b0),
          "f"(0.f), "f"(0.f), "f"(0.f), "f"(0.f));
}
// mma.m16n8k16 f16 inputs, f32 accum
__device__ __forceinline__ void mma_k16h(float* d, u32 a0, u32 a1, u32 a2, u32 a3,
                                         u32 b0, u32 b1) {
    asm volatile(
        "mma.sync.aligned.m16n8k16.row.col.f32.f16.f16.f32 "
        "{%0,%1,%2,%3}, {%4,%5,%6,%7}, {%8,%9}, {%0,%1,%2,%3};\n"
        : "+f"(d[0]), "+f"(d[1]), "+f"(d[2]), "+f"(d[3])
        : "r"(a0), "r"(a1), "r"(a2), "r"(a3), "r"(b0), "r"(b1));
}
// mma.m16n8k16 f16 inputs, f16 accum
__device__ __forceinline__ void mma_k16hh(u32& d0, u32& d1, u32 a0, u32 a1, u32 a2, u32 a3,
                                          u32 b0, u32 b1) {
    asm volatile(
        "mma.sync.aligned.m16n8k16.row.col.f16.f16.f16.f16 "
        "{%0,%1}, {%2,%3,%4,%5}, {%6,%7}, {%0,%1};\n"
        : "+r"(d0), "+r"(d1)
        : "r"(a0), "r"(a1), "r"(a2), "r"(a3), "r"(b0), "r"(b1));
}
__device__ __forceinline__ void ldsm_x4(u32& r0, u32& r1, u32& r2, u32& r3, u32 a) {
    asm volatile("ldmatrix.sync.aligned.m8n8.x4.shared.b16 {%0,%1,%2,%3}, [%4];"
                 : "=r"(r0), "=r"(r1), "=r"(r2), "=r"(r3) : "r"(a));
}
__device__ __forceinline__ void ldsm_x2(u32& r0, u32& r1, u32 a) {
    asm volatile("ldmatrix.sync.aligned.m8n8.x2.shared.b16 {%0,%1}, [%2];"
                 : "=r"(r0), "=r"(r1) : "r"(a));
}
__device__ __forceinline__ void ldsm_x4_t(u32& r0, u32& r1, u32& r2, u32& r3, u32 a) {
    asm volatile("ldmatrix.sync.aligned.m8n8.x4.trans.shared.b16 {%0,%1,%2,%3}, [%4];"
                 : "=r"(r0), "=r"(r1), "=r"(r2), "=r"(r3) : "r"(a));
}

// ---------------- kernel 1: projections (tensor cores) + fused 2x2 pool ----------------
static constexpr int XS_S = 136;
static constexpr int WS_S = 72;
static constexpr int DS_S = 56;

__global__ void __launch_bounds__(256) proj_kernel(
    const float* __restrict__ x,
    const float* __restrict__ Wt, const float* __restrict__ Wp,
    const float* __restrict__ Wg)
{
    __shared__ __align__(16) __half xs [64 * XS_S];
    __shared__ __align__(16) __half Ws [48 * WS_S];
    __shared__ __align__(16) __half dsm[128 * DS_S];

    int tid = threadIdx.x;
    int b   = blockIdx.y;
    int r   = blockIdx.x;          // pooled row
    int p0  = r * 128;

    for (int i = tid; i < 1536; i += 256) {
        int j = i >> 5, cp = i & 31;
        const float* Wsrc = (j < 8) ? &Wt[j * 64]
                          : (j < 16) ? &Wp[(j - 8) * 64]
                                     : &Wg[(j - 16) * 64];
        float2 v = *reinterpret_cast<const float2*>(&Wsrc[2 * cp]);
        *reinterpret_cast<u32*>(&Ws[j * WS_S + 2 * cp]) = packh(v.x, v.y);
    }
    const float* xb = x + (size_t)b * 64 * HW_ + p0;
#pragma unroll
    for (int it = 0; it < 16; it++) {
        int flat = it * 256 + tid;
        int c = flat >> 6, pp = flat & 63;
        float2 v = *reinterpret_cast<const float2*>(&xb[(size_t)c * HW_ + 2 * pp]);
        *reinterpret_cast<u32*>(&xs[c * XS_S + 2 * pp]) = packh(v.x, v.y);
    }
    __syncthreads();

    int w = tid >> 5, lane = tid & 31;
    int g4 = lane >> 2, tg = lane & 3;
    int pw = w * 16;

    int mi = lane >> 3, rr = lane & 7;
    int half8 = (mi & 1) * 8;
    int oth8  = (mi >> 1) * 8;
    u32 xs_a = (u32)__cvta_generic_to_shared(xs);
    u32 ws_a = (u32)__cvta_generic_to_shared(Ws);
    u32 b_base = xs_a + ((half8 + rr) * XS_S + pw + oth8) * 2;

    float acc[3][2][4];
#pragma unroll
    for (int m = 0; m < 3; m++)
#pragma unroll
        for (int n = 0; n < 2; n++)
#pragma unroll
            for (int e = 0; e < 4; e++) acc[m][n][e] = 0.f;

#pragma unroll
    for (int ks = 0; ks < 4; ks++) {
        int k0 = ks * 16;
        u32 b0n0, b1n0, b0n1, b1n1;
        ldsm_x4_t(b0n0, b1n0, b0n1, b1n1, b_base + k0 * XS_S * 2);
#pragma unroll
        for (int m = 0; m < 3; m++) {
            u32 A0, A1, A2, A3;
            ldsm_x4(A0, A1, A2, A3,
                    ws_a + ((m * 16 + half8 + rr) * WS_S + k0 + oth8) * 2);
            mma_k16h(acc[m][0], A0, A1, A2, A3, b0n0, b1n0);
            mma_k16h(acc[m][1], A0, A1, A2, A3, b0n1, b1n1);
        }
    }

#pragma unroll
    for (int m = 0; m < 3; m++)
#pragma unroll
        for (int nt = 0; nt < 2; nt++) {
            int j = m * 16 + g4;
            int p = pw + nt * 8 + 2 * tg;
            dsm[p * DS_S + j]           = __float2half(acc[m][nt][0]);
            dsm[(p + 1) * DS_S + j]     = __float2half(acc[m][nt][1]);
            dsm[p * DS_S + j + 8]       = __float2half(acc[m][nt][2]);
            dsm[(p + 1) * DS_S + j + 8] = __float2half(acc[m][nt][3]);
        }
    __syncthreads();

    if (tid < 128) {
        reinterpret_cast<uint4*>(d_theta)[(size_t)b * HW_ + p0 + tid] =
            *reinterpret_cast<const uint4*>(&dsm[tid * DS_S]);
        if (tid >= 96) {
            int j2 = tid - 96;
            int pA = 2 * j2, pC = 64 + 2 * j2;
            uint4 m = max4u(*reinterpret_cast<const uint4*>(&dsm[pA * DS_S + 8]),
                            *reinterpret_cast<const uint4*>(&dsm[(pA + 1) * DS_S + 8]),
                            *reinterpret_cast<const uint4*>(&dsm[pC * DS_S + 8]),
                            *reinterpret_cast<const uint4*>(&dsm[(pC + 1) * DS_S + 8]));
            reinterpret_cast<uint4*>(d_phi_t)[(size_t)b * SP_ + r * 32 + j2] = m;
        }
    } else {
        int i  = tid - 128;
        int j2 = i & 31, vq = i >> 5;
        int pA = 2 * j2, pC = 64 + 2 * j2;
        int off = 16 + 8 * vq;
        uint4 m = max4u(*reinterpret_cast<const uint4*>(&dsm[pA * DS_S + off]),
                        *reinterpret_cast<const uint4*>(&dsm[(pA + 1) * DS_S + off]),
                        *reinterpret_cast<const uint4*>(&dsm[pC * DS_S + off]),
                        *reinterpret_cast<const uint4*>(&dsm[(pC + 1) * DS_S + off]));
        int s = r * 32 + j2;
        __half* gt = d_g_t + ((size_t)b * 32 << 10) + s;
        const __half2* h = reinterpret_cast<const __half2*>(&m);
#pragma unroll
        for (int e = 0; e < 4; e++) {
            int v = vq * 8 + 2 * e;
            gt[(size_t)v << 10]       = __low2half(h[e]);
            gt[(size_t)(v + 1) << 10] = __high2half(h[e]);
        }
    }
}

// ---------------- kernel 2: fused attention + output projection + residual ----------------
// R14 champion shape (256 thr, 256 q/CTA, 2 q-tiles/warp, 2 key chunks, ldmatrix).
// Chain de-exposure: phi LDSM prefetched 1 iter ahead; g LDSMs issued right after
// QK mmas (overlap exp); sum mmas issued after PV mmas (off critical path).
static constexpr int KC       = 512;
static constexpr int G_STRIDE = 520;
static constexpr int ATTN_SMEM = KC * 8 * 2 + 32 * G_STRIDE * 2;  // 41472
static constexpr int OSM_S = 40;
static constexpr int WO_S  = 34;

__global__ void __launch_bounds__(256, 3) attn_out_kernel(
    const float* __restrict__ x, const float* __restrict__ Wo,
    const float* __restrict__ gamma_p, float* __restrict__ out)
{
    extern __shared__ __align__(16) char smem[];
    __half* phi_s = reinterpret_cast<__half*>(smem);               // [key][8]
    __half* g_s   = reinterpret_cast<__half*>(smem + KC * 8 * 2);  // [v][520]
    // epilogue overlays:
    __half* osm = reinterpret_cast<__half*>(smem);                 // 256*40*2 = 20480 B
    __half* wsm = reinterpret_cast<__half*>(smem + 20480);         // 64*34*2  =  4352 B

    int b   = blockIdx.y;
    int tid = threadIdx.x;

    int w    = tid >> 5;
    int lane = tid & 31;
    int g4   = lane >> 2;
    int tg   = lane & 3;
    int qb   = blockIdx.x * 256 + w * 32;   // 2 q-tiles per warp
    int q0   = qb + g4;
    int q1   = qb + 16 + g4;

    const __half* th = d_theta + (size_t)(b * HW_) * 8;
    u32 a0 = *reinterpret_cast<const u32*>(th + (size_t)q0 * 8 + 2 * tg);
    u32 a1 = *reinterpret_cast<const u32*>(th + (size_t)(q0 + 8) * 8 + 2 * tg);
    u32 a2 = *reinterpret_cast<const u32*>(th + (size_t)q1 * 8 + 2 * tg);
    u32 a3 = *reinterpret_cast<const u32*>(th + (size_t)(q1 + 8) * 8 + 2 * tg);

    const u32 ONES = 0x3C003C00u;  // f16x2 {1,1}

    u32 o0[8], o1[8];
#pragma unroll
    for (int i = 0; i < 8; i++) { o0[i] = 0u; o1[i] = 0u; }
    u32 sm0[2] = {0u, 0u}, sm1[2] = {0u, 0u};

    // ldmatrix lane addresses
    u32 phi_a0 = (u32)__cvta_generic_to_shared(phi_s) + (lane & 15) * 16;
    int mrow = lane >> 3, rrow = lane & 7;
    int v0   = (mrow >> 1) * 8 + rrow;
    int cofs = (mrow & 1) * 8;
    u32 g_a0 = (u32)__cvta_generic_to_shared(g_s) + (v0 * G_STRIDE + cofs) * 2;
    u32 g_a1 = g_a0 + 16 * G_STRIDE * 2;

#pragma unroll 1
    for (int chunk = 0; chunk < 2; chunk++) {
        if (chunk) __syncthreads();   // prior chunk fully consumed before overwrite
        // load phi chunk: 512 keys * 16B
        {
            const uint4* src = reinterpret_cast<const uint4*>(d_phi_t)
                               + (size_t)b * SP_ + chunk * KC;
            uint4* dst = reinterpret_cast<uint4*>(phi_s);
#pragma unroll
            for (int it = 0; it < 2; it++) dst[it * 256 + tid] = src[it * 256 + tid];
        }
        // load g chunk: 32 rows x 64 uint4 -> padded rows of 65 uint4
        {
            const uint4* src = reinterpret_cast<const uint4*>(d_g_t)
                               + (size_t)b * 32 * 128 + chunk * 64;
            uint4* dst = reinterpret_cast<uint4*>(g_s);
#pragma unroll
            for (int it = 0; it < 8; it++) {
                int i = it * 256 + tid;
                int v = i >> 6, col = i & 63;
                dst[v * 65 + col] = src[v * 128 + col];
            }
        }
        __syncthreads();

        // prologue: prefetch phi fragments for kb=0
        u32 pb0, pb1;
        ldsm_x2(pb0, pb1, phi_a0);

#pragma unroll 2
        for (int kb = 0; kb < KC; kb += 16) {
            // QK mmas (consume prefetched phi fragments)
            float s0[4], s1v[4], s2[4], s3[4];
            mma_k8h(s0,  a0, a1, pb0);
            mma_k8h(s1v, a0, a1, pb1);
            mma_k8h(s2,  a2, a3, pb0);
            mma_k8h(s3,  a2, a3, pb1);

            // g LDSMs issue now: latency overlaps QK mma + exp below
            u32 gA0, gA1, gA2, gA3, gB0, gB1, gB2, gB3;
            ldsm_x4(gA0, gA1, gA2, gA3, g_a0 + kb * 2);
            ldsm_x4(gB0, gB1, gB2, gB3, g_a1 + kb * 2);

            // prefetch phi for next iteration (overlaps everything below)
            if (kb + 16 < KC) ldsm_x2(pb0, pb1, phi_a0 + (kb + 16) * 16);

            u32 pa0 = fexp2pack(s0[0],  s0[1]);
            u32 pa1 = fexp2pack(s0[2],  s0[3]);
            u32 pa2 = fexp2pack(s1v[0], s1v[1]);
            u32 pa3 = fexp2pack(s1v[2], s1v[3]);
            u32 qa0 = fexp2pack(s2[0],  s2[1]);
            u32 qa1 = fexp2pack(s2[2],  s2[3]);
            u32 qa2 = fexp2pack(s3[0],  s3[1]);
            u32 qa3 = fexp2pack(s3[2],  s3[3]);

            // PV first (critical path), sums after (not consumed until end)
            mma_k16hh(o0[0], o0[1], pa0, pa1, pa2, pa3, gA0, gA1);
            mma_k16hh(o0[2], o0[3], pa0, pa1, pa2, pa3, gA2, gA3);
            mma_k16hh(o0[4], o0[5], pa0, pa1, pa2, pa3, gB0, gB1);
            mma_k16hh(o0[6], o0[7], pa0, pa1, pa2, pa3, gB2, gB3);
            mma_k16hh(o1[0], o1[1], qa0, qa1, qa2, qa3, gA0, gA1);
            mma_k16hh(o1[2], o1[3], qa0, qa1, qa2, qa3, gA2, gA3);
            mma_k16hh(o1[4], o1[5], qa0, qa1, qa2, qa3, gB0, gB1);
            mma_k16hh(o1[6], o1[7], qa0, qa1, qa2, qa3, gB2, gB3);

            mma_k16hh(sm0[0], sm0[1], pa0, pa1, pa2, pa3, ONES, ONES);
            mma_k16hh(sm1[0], sm1[1], qa0, qa1, qa2, qa3, ONES, ONES);
        }
    }

    float gm = *gamma_p;
    float iA0 = __fdividef(gm, __low2float(*reinterpret_cast<__half2*>(&sm0[0])));
    float iA1 = __fdividef(gm, __low2float(*reinterpret_cast<__half2*>(&sm0[1])));
    float iB0 = __fdividef(gm, __low2float(*reinterpret_cast<__half2*>(&sm1[0])));
    float iB1 = __fdividef(gm, __low2float(*reinterpret_cast<__half2*>(&sm1[1])));

    // ---- stage normalized, gamma-folded o into smem (overlay) ----
    __syncthreads();
    {
        int ql0 = w * 32 + g4;
        int ql1 = w * 32 + 16 + g4;
#pragma unroll
        for (int j = 0; j < 4; j++) {
            int v = 8 * j + 2 * tg;
            float2 f;
            f = __half22float2(*reinterpret_cast<__half2*>(&o0[2 * j]));
            *reinterpret_cast<u32*>(&osm[ql0 * OSM_S + v]) = packh(f.x * iA0, f.y * iA0);
            f = __half22float2(*reinterpret_cast<__half2*>(&o0[2 * j + 1]));
            *reinterpret_cast<u32*>(&osm[(ql0 + 8) * OSM_S + v]) = packh(f.x * iA1, f.y * iA1);
            f = __half22float2(*reinterpret_cast<__half2*>(&o1[2 * j]));
            *reinterpret_cast<u32*>(&osm[ql1 * OSM_S + v]) = packh(f.x * iB0, f.y * iB0);
            f = __half22float2(*reinterpret_cast<__half2*>(&o1[2 * j + 1]));
            *reinterpret_cast<u32*>(&osm[(ql1 + 8) * OSM_S + v]) = packh(f.x * iB1, f.y * iB1);
        }
    }
    for (int i = tid; i < 64 * 32; i += 256) {
        int c = i >> 5, v = i & 31;
        wsm[c * WO_S + v] = __float2half(Wo[c * 32 + v]);
    }
    __syncthreads();

    // ---- epilogue: out[c][p] = Wo @ o^T + x (register-light, per-m tiles) ----
    int p0 = blockIdx.x * 256;
    const float* xb = x + (size_t)b * 64 * HW_;
    float* outb     = out + (size_t)b * 64 * HW_;

#pragma unroll 1
    for (int hh = 0; hh < 2; hh++) {
        int ph = w * 32 + hh * 16;

        u32 Bf[2][2][2];
#pragma unroll
        for (int nt = 0; nt < 2; nt++) {
            int qr = (ph + nt * 8 + g4) * OSM_S;
#pragma unroll
            for (int ks = 0; ks < 2; ks++) {
                Bf[nt][ks][0] = *reinterpret_cast<const u32*>(&osm[qr + ks * 16 + 2 * tg]);
                Bf[nt][ks][1] = *reinterpret_cast<const u32*>(&osm[qr + ks * 16 + 8 + 2 * tg]);
            }
        }

#pragma unroll
        for (int m = 0; m < 4; m++) {
            float acc[2][4];
#pragma unroll
            for (int n = 0; n < 2; n++)
#pragma unroll
                for (int e = 0; e < 4; e++) acc[n][e] = 0.f;

#pragma unroll
            for (int ks = 0; ks < 2; ks++) {
                int r0 = (m * 16 + g4) * WO_S + ks * 16 + 2 * tg;
                int r1 = (m * 16 + g4 + 8) * WO_S + ks * 16 + 2 * tg;
                u32 A0 = *reinterpret_cast<const u32*>(&wsm[r0]);
                u32 A1 = *reinterpret_cast<const u32*>(&wsm[r1]);
                u32 A2 = *reinterpret_cast<const u32*>(&wsm[r0 + 8]);
                u32 A3 = *reinterpret_cast<const u32*>(&wsm[r1 + 8]);
                mma_k16h(acc[0], A0, A1, A2, A3, Bf[0][ks][0], Bf[0][ks][1]);
                mma_k16h(acc[1], A0, A1, A2, A3, Bf[1][ks][0], Bf[1][ks][1]);
            }

#pragma unroll
            for (int nt = 0; nt < 2; nt++) {
                int c = m * 16 + g4;
                int p = p0 + ph + nt * 8 + 2 * tg;
                size_t i1 = (size_t)c * HW_ + p;
                size_t i2 = (size_t)(c + 8) * HW_ + p;
                float2 xv1 = *reinterpret_cast<const float2*>(&xb[i1]);
                float2 xv2 = *reinterpret_cast<const float2*>(&xb[i2]);
                float2 r1 = make_float2(acc[nt][0] + xv1.x, acc[nt][1] + xv1.y);
                float2 r2 = make_float2(acc[nt][2] + xv2.x, acc[nt][3] + xv2.y);
                *reinterpret_cast<float2*>(&outb[i1]) = r1;
                *reinterpret_cast<float2*>(&outb[i2]) = r2;
            }
        }
    }
}

// ---------------- launch ----------------
extern "C" void kernel_launch(void* const* d_in, const int* in_sizes, int n_in,
                              void* d_out, int out_size)
{
    const float* x     = (const float*)d_in[0];
    const float* Wt    = (const float*)d_in[1];
    const float* Wp    = (const float*)d_in[2];
    const float* Wg    = (const float*)d_in[3];
    const float* Wo    = (const float*)d_in[4];
    const float* gamma = (const float*)d_in[5];
    float* out = (float*)d_out;

    proj_kernel<<<dim3(32, 16), 256>>>(x, Wt, Wp, Wg);

    cudaFuncSetAttribute(attn_out_kernel, cudaFuncAttributeMaxDynamicSharedMemorySize, ATTN_SMEM);
    attn_out_kernel<<<dim3(16, 16), 256, ATTN_SMEM>>>(x, Wo, gamma, out);
}